// round 1
// baseline (speedup 1.0000x reference)
#include <cuda_runtime.h>

// FastText embedding-bag:
//   out[b, :] = W_in[center_ids[b], :] + sum_{i: segment_ids[i]==b} W_sub[ngram_idx[i], :]
// segment_ids sorted ascending -> per-row contiguous range found by binary search.
// D = 300 floats = 75 float4 per row (rows are 1200 B, 16-B aligned).

#define D4 75  // 300 / 4

__global__ void __launch_bounds__(96, 16)
ft_bag_kernel(const int* __restrict__ center,
              const int* __restrict__ ngram,
              const int* __restrict__ seg,
              const float4* __restrict__ Win,
              const float4* __restrict__ Wsub,
              float4* __restrict__ out,
              int total)
{
    const int b = blockIdx.x;
    const int t = threadIdx.x;

    __shared__ int s_lo, s_hi;

    // Two threads do the two lower_bound searches in parallel.
    if (t < 2) {
        const int target = b + t;           // t==0: lower_bound(b), t==1: lower_bound(b+1)
        int lo = 0, hi = total;
        while (lo < hi) {
            int m = (lo + hi) >> 1;
            if (__ldg(seg + m) < target) lo = m + 1;
            else                         hi = m;
        }
        if (t == 0) s_lo = lo; else s_hi = lo;
    }
    __syncthreads();

    if (t >= D4) return;

    const int lo = s_lo;
    const int hi = s_hi;

    // word vector
    const long long crow = (long long)__ldg(center + b) * D4;
    float4 acc = __ldg(Win + crow + t);

    // ragged subword sum; unroll by 2 for index-load / row-load overlap
    int i = lo;
    for (; i + 1 < hi; i += 2) {
        const long long r0 = (long long)__ldg(ngram + i)     * D4;
        const long long r1 = (long long)__ldg(ngram + i + 1) * D4;
        float4 v0 = __ldg(Wsub + r0 + t);
        float4 v1 = __ldg(Wsub + r1 + t);
        acc.x += v0.x + v1.x;
        acc.y += v0.y + v1.y;
        acc.z += v0.z + v1.z;
        acc.w += v0.w + v1.w;
    }
    if (i < hi) {
        const long long r = (long long)__ldg(ngram + i) * D4;
        float4 v = __ldg(Wsub + r + t);
        acc.x += v.x; acc.y += v.y; acc.z += v.z; acc.w += v.w;
    }

    out[(long long)b * D4 + t] = acc;
}

extern "C" void kernel_launch(void* const* d_in, const int* in_sizes, int n_in,
                              void* d_out, int out_size)
{
    // metadata order: center_ids(int32,B), ngram_idx(int32,TOTAL),
    //                 segment_ids(int32,TOTAL), W_in(f32,VOCAB*D), W_sub(f32,BUCKET*D)
    const int*    center = (const int*)d_in[0];
    const int*    ngram  = (const int*)d_in[1];
    const int*    seg    = (const int*)d_in[2];
    const float4* Win    = (const float4*)d_in[3];
    const float4* Wsub   = (const float4*)d_in[4];
    float4*       out    = (float4*)d_out;

    const int B     = in_sizes[0];
    const int total = in_sizes[1];

    ft_bag_kernel<<<B, 96>>>(center, ngram, seg, Win, Wsub, out, total);
}

// round 2
// speedup vs baseline: 1.2178x; 1.2178x over previous
#include <cuda_runtime.h>

// FastText embedding-bag:
//   out[b, :] = W_in[center_ids[b], :] + sum_{i: segment_ids[i]==b} W_sub[ngram_idx[i], :]
// segment_ids sorted ascending -> per-row contiguous range via binary search.
// D = 300 floats = 75 float4 per row (1200 B rows, 16-B aligned).
//
// R2: stage ngram indices into smem (kills the idx->row dependent-load chain),
//     unroll row loads by 4 with independent registers for high MLP.

#define D4 75          // 300 / 4
#define CHUNK 64       // indices staged per smem pass

__global__ void __launch_bounds__(96)
ft_bag_kernel(const int* __restrict__ center,
              const int* __restrict__ ngram,
              const int* __restrict__ seg,
              const float4* __restrict__ Win,
              const float4* __restrict__ Wsub,
              float4* __restrict__ out,
              int total)
{
    const int b = blockIdx.x;
    const int t = threadIdx.x;

    __shared__ int s_lo, s_hi;
    __shared__ int s_idx[CHUNK];

    // Two threads run the two lower_bound searches in parallel.
    if (t < 2) {
        const int target = b + t;
        int lo = 0, hi = total;
        while (lo < hi) {
            int m = (lo + hi) >> 1;
            if (__ldg(seg + m) < target) lo = m + 1;
            else                         hi = m;
        }
        if (t == 0) s_lo = lo; else s_hi = lo;
    }
    __syncthreads();

    const int lo = s_lo;
    const int hi = s_hi;
    const bool act = (t < D4);

    // word vector — issued early, overlaps with first index staging
    float4 acc = make_float4(0.f, 0.f, 0.f, 0.f);
    if (act) {
        const long long crow = (long long)__ldg(center + b) * D4;
        acc = __ldg(Win + crow + t);
    }

    for (int base = lo; base < hi; base += CHUNK) {
        const int n = min(hi - base, CHUNK);

        if (t < n) s_idx[t] = __ldg(ngram + base + t);
        __syncthreads();

        if (act) {
            int j = 0;
            #pragma unroll 1
            for (; j + 3 < n; j += 4) {
                const long long r0 = (long long)s_idx[j]     * D4;
                const long long r1 = (long long)s_idx[j + 1] * D4;
                const long long r2 = (long long)s_idx[j + 2] * D4;
                const long long r3 = (long long)s_idx[j + 3] * D4;
                float4 v0 = __ldg(Wsub + r0 + t);
                float4 v1 = __ldg(Wsub + r1 + t);
                float4 v2 = __ldg(Wsub + r2 + t);
                float4 v3 = __ldg(Wsub + r3 + t);
                acc.x += (v0.x + v1.x) + (v2.x + v3.x);
                acc.y += (v0.y + v1.y) + (v2.y + v3.y);
                acc.z += (v0.z + v1.z) + (v2.z + v3.z);
                acc.w += (v0.w + v1.w) + (v2.w + v3.w);
            }
            for (; j < n; j++) {
                const long long r = (long long)s_idx[j] * D4;
                float4 v = __ldg(Wsub + r + t);
                acc.x += v.x; acc.y += v.y; acc.z += v.z; acc.w += v.w;
            }
        }
        __syncthreads();   // protect s_idx before next chunk overwrite
    }

    if (act) out[(long long)b * D4 + t] = acc;
}

extern "C" void kernel_launch(void* const* d_in, const int* in_sizes, int n_in,
                              void* d_out, int out_size)
{
    const int*    center = (const int*)d_in[0];
    const int*    ngram  = (const int*)d_in[1];
    const int*    seg    = (const int*)d_in[2];
    const float4* Win    = (const float4*)d_in[3];
    const float4* Wsub   = (const float4*)d_in[4];
    float4*       out    = (float4*)d_out;

    const int B     = in_sizes[0];
    const int total = in_sizes[1];

    ft_bag_kernel<<<B, 96>>>(center, ngram, seg, Win, Wsub, out, total);
}